// round 1
// baseline (speedup 1.0000x reference)
#include <cuda_runtime.h>
#include <cuda_bf16.h>
#include <math.h>
#include <stddef.h>

// Problem constants
#define Bsz   2048
#define Nn    20
#define Dd    512
#define Hh    8
#define DKk   64
#define DQq   64
#define Mrows (Bsz*Nn)     // 40960
#define K3    (3*Dd)       // 1536

// -------- scratch (static __device__, no allocation) --------
__device__ float g_Wcat[(size_t)K3 * K3];            // 9.4 MB  [kk][oc]
__device__ float g_conv[(size_t)Mrows * K3];         // 252 MB  conv GEMM out
__device__ float g_qkv[(size_t)3 * Mrows * Dd];      // 252 MB  q,k,v after LN+res
__device__ float g_qp[(size_t)Mrows * Hh];           // 1.3 MB
__device__ float g_attn[(size_t)Mrows * Dd];         // 84 MB

// ============================================================
// Weight repack: Wcat[kk=t*512+i][oc=p*512+o] = W_p[o, i, t]
// ============================================================
__global__ void repack_w(const float* __restrict__ Wq,
                         const float* __restrict__ Wk,
                         const float* __restrict__ Wv)
{
    int idx = blockIdx.x * 256 + threadIdx.x;
    if (idx >= K3 * K3) return;
    int kk = idx / K3;
    int oc = idx - kk * K3;
    int t = kk >> 9;             // kk / 512
    int i = kk & 511;
    int p = oc >> 9;
    int o = oc & 511;
    const float* W = (p == 0) ? Wq : (p == 1) ? Wk : Wv;
    g_Wcat[idx] = W[(size_t)o * K3 + i * 3 + t];
}

// ============================================================
// Tiled fp32 GEMM.  MODE=1: A is im2col of x (conv gather).
// All dims divide tiles evenly (M=40960, N in {1536,512}, K in {1536,512}).
// ============================================================
#define BM 128
#define BN 128
#define BKt 16

template<int MODE, bool BIAS>
__global__ __launch_bounds__(256)
void sgemm_kernel(const float* __restrict__ A, const float* __restrict__ Bm,
                  float* __restrict__ C, const float* __restrict__ bias,
                  int M, int N, int K)
{
    __shared__ float As[BKt][BM];
    __shared__ float Bs[BKt][BN];

    const int tid  = threadIdx.x;
    const int tx   = tid & 15;
    const int ty   = tid >> 4;
    const int row0 = blockIdx.y * BM;
    const int col0 = blockIdx.x * BN;

    const int arow  = tid >> 1;         // 0..127
    const int acol0 = (tid & 1) << 3;   // 0 or 8
    const int brow  = tid >> 4;         // 0..15
    const int bcol0 = (tid & 15) << 3;  // 0..120

    float acc[8][8];
    #pragma unroll
    for (int i = 0; i < 8; i++)
        #pragma unroll
        for (int j = 0; j < 8; j++) acc[i][j] = 0.f;

    for (int kt = 0; kt < K; kt += BKt) {
        // ---- load A tile (128 x 16) ----
        #pragma unroll
        for (int i = 0; i < 8; i++) {
            int acol = acol0 + i;
            int kk = kt + acol;
            float v;
            if (MODE == 1) {
                // im2col: row m=(b,n), kk = t*512 + d -> x[b, n+t-1, d] (zero pad)
                int gm = row0 + arow;
                int t  = kk >> 9;
                int d  = kk & 511;
                int bb = gm / Nn;
                int nn = gm - bb * Nn;
                int jj = nn + t - 1;
                v = (jj >= 0 && jj < Nn) ? A[((size_t)bb * Nn + jj) * Dd + d] : 0.f;
            } else {
                v = A[(size_t)(row0 + arow) * K + kk];
            }
            As[acol][arow] = v;
        }
        // ---- load B tile (16 x 128) ----
        #pragma unroll
        for (int i = 0; i < 8; i++) {
            Bs[brow][bcol0 + i] = Bm[(size_t)(kt + brow) * N + col0 + bcol0 + i];
        }
        __syncthreads();

        #pragma unroll
        for (int k = 0; k < BKt; k++) {
            float ar[8], br[8];
            #pragma unroll
            for (int i = 0; i < 8; i++) ar[i] = As[k][ty * 8 + i];
            #pragma unroll
            for (int j = 0; j < 8; j++) br[j] = Bs[k][tx * 8 + j];
            #pragma unroll
            for (int i = 0; i < 8; i++)
                #pragma unroll
                for (int j = 0; j < 8; j++) acc[i][j] += ar[i] * br[j];
        }
        __syncthreads();
    }

    #pragma unroll
    for (int i = 0; i < 8; i++) {
        int r = row0 + ty * 8 + i;
        #pragma unroll
        for (int j = 0; j < 8; j++) {
            int c = col0 + tx * 8 + j;
            float v = acc[i][j];
            if (BIAS) v += bias[c];
            C[(size_t)r * N + c] = v;
        }
    }
}

// ============================================================
// LayerNorm + residual.  One block per (proj p, row m).
// q/k/v = x + LN(conv_out_p) * g + b
// ============================================================
__global__ __launch_bounds__(256)
void ln_res_kernel(const float* __restrict__ xin,
                   const float* __restrict__ gq_g, const float* __restrict__ gq_b,
                   const float* __restrict__ gk_g, const float* __restrict__ gk_b,
                   const float* __restrict__ gv_g, const float* __restrict__ gv_b)
{
    int bl = blockIdx.x;            // 0 .. 3*Mrows-1
    int p  = bl / Mrows;
    int m  = bl - p * Mrows;
    int tid = threadIdx.x;

    const float* y = g_conv + (size_t)m * K3 + p * Dd;
    float v0 = y[tid];
    float v1 = y[tid + 256];

    __shared__ float rs[256], rq[256];
    rs[tid] = v0 + v1;
    rq[tid] = v0 * v0 + v1 * v1;
    __syncthreads();
    for (int s = 128; s > 0; s >>= 1) {
        if (tid < s) { rs[tid] += rs[tid + s]; rq[tid] += rq[tid + s]; }
        __syncthreads();
    }
    float mean = rs[0] * (1.f / 512.f);
    float var  = rq[0] * (1.f / 512.f) - mean * mean;
    float rstd = rsqrtf(var + 1e-5f);

    const float* g  = (p == 0) ? gq_g : (p == 1) ? gk_g : gv_g;
    const float* bb = (p == 0) ? gq_b : (p == 1) ? gk_b : gv_b;
    float* out = g_qkv + (size_t)p * Mrows * Dd + (size_t)m * Dd;
    const float* xr = xin + (size_t)m * Dd;

    out[tid]       = xr[tid]       + (v0 - mean) * rstd * g[tid]       + bb[tid];
    out[tid + 256] = xr[tid + 256] + (v1 - mean) * rstd * g[tid + 256] + bb[tid + 256];
}

// ============================================================
// qp[b,n,h] = tanh(x[b,n,:] @ Wqf + bqf) @ Wqp
// (dyn bias factorizes: dyn[b,h,n,m] = qp[n,h] - qp[m,h] + bqp[h])
// 8 rows per block of 64 threads to amortize Wqf traffic.
// ============================================================
__global__ __launch_bounds__(64)
void qp_kernel(const float* __restrict__ x, const float* __restrict__ Wqf,
               const float* __restrict__ bqf, const float* __restrict__ Wqp)
{
    __shared__ float xs[8][512];
    __shared__ float qf[8][64];
    int m0 = blockIdx.x * 8;
    int tid = threadIdx.x;

    for (int i = tid; i < 8 * 512; i += 64)
        xs[i >> 9][i & 511] = x[(size_t)m0 * 512 + i];
    __syncthreads();

    float acc[8];
    float bq = bqf[tid];
    #pragma unroll
    for (int r = 0; r < 8; r++) acc[r] = bq;
    for (int i = 0; i < 512; i++) {
        float w = Wqf[i * 64 + tid];
        #pragma unroll
        for (int r = 0; r < 8; r++) acc[r] += xs[r][i] * w;
    }
    #pragma unroll
    for (int r = 0; r < 8; r++) qf[r][tid] = tanhf(acc[r]);
    __syncthreads();

    int r = tid >> 3, h = tid & 7;
    float a = 0.f;
    #pragma unroll
    for (int t = 0; t < 64; t++) a += qf[r][t] * Wqp[t * 8 + h];
    g_qp[(size_t)(m0 + r) * 8 + h] = a;
}

// ============================================================
// Attention: one block per (b,h).  N=20 fits entirely in smem.
// ============================================================
__global__ __launch_bounds__(256)
void attn_kernel(const float* __restrict__ rel_table,
                 const float* __restrict__ gsb,
                 const float* __restrict__ alpha_p,
                 const float* __restrict__ bqp)
{
    int b = blockIdx.x >> 3;
    int h = blockIdx.x & 7;
    int tid = threadIdx.x;

    __shared__ float qs[Nn * 64], ks[Nn * 64], vs[Nn * 64];
    __shared__ float sc[Nn][Nn];
    __shared__ float relh[2 * Nn - 1];
    __shared__ float qph[Nn];

    const size_t QOFF = 0;
    const size_t KOFF = (size_t)Mrows * Dd;
    const size_t VOFF = (size_t)2 * Mrows * Dd;

    for (int i = tid; i < Nn * 64; i += 256) {
        int n = i >> 6, d = i & 63;
        size_t src = (size_t)(b * Nn + n) * Dd + h * 64 + d;
        qs[i] = g_qkv[QOFF + src];
        ks[i] = g_qkv[KOFF + src];
        vs[i] = g_qkv[VOFF + src];
    }
    if (tid < 2 * Nn - 1) relh[tid] = rel_table[tid * Hh + h];
    if (tid < Nn)         qph[tid]  = g_qp[(size_t)(b * Nn + tid) * Hh + h];
    __syncthreads();

    float alpha = *alpha_p;
    float bq = bqp[h];

    for (int i = tid; i < Nn * Nn; i += 256) {
        int n = i / Nn, m = i - n * Nn;
        float a = 0.f;
        #pragma unroll
        for (int d = 0; d < 64; d++) a += qs[n * 64 + d] * ks[m * 64 + d];
        a = a * 0.125f
          + relh[n - m + Nn - 1]
          + alpha * gsb[(size_t)(h * Nn + n) * Nn + m]
          + (qph[n] - qph[m]) + bq;
        sc[n][m] = a;
    }
    __syncthreads();

    if (tid < Nn) {
        float mx = -1e30f;
        #pragma unroll
        for (int m = 0; m < Nn; m++) mx = fmaxf(mx, sc[tid][m]);
        float s = 0.f;
        #pragma unroll
        for (int m = 0; m < Nn; m++) { float e = expf(sc[tid][m] - mx); sc[tid][m] = e; s += e; }
        float inv = 1.f / s;
        #pragma unroll
        for (int m = 0; m < Nn; m++) sc[tid][m] *= inv;
    }
    __syncthreads();

    for (int i = tid; i < Nn * 64; i += 256) {
        int n = i >> 6, d = i & 63;
        float a = 0.f;
        #pragma unroll
        for (int m = 0; m < Nn; m++) a += sc[n][m] * vs[m * 64 + d];
        g_attn[(size_t)(b * Nn + n) * Dd + h * 64 + d] = a;
    }
}

// ============================================================
// launch
// ============================================================
extern "C" void kernel_launch(void* const* d_in, const int* in_sizes, int n_in,
                              void* d_out, int out_size)
{
    const float* x         = (const float*)d_in[0];
    const float* Wq        = (const float*)d_in[1];
    const float* Wk        = (const float*)d_in[2];
    const float* Wv        = (const float*)d_in[3];
    const float* gq_g      = (const float*)d_in[4];
    const float* gq_b      = (const float*)d_in[5];
    const float* gk_g      = (const float*)d_in[6];
    const float* gk_b      = (const float*)d_in[7];
    const float* gv_g      = (const float*)d_in[8];
    const float* gv_b      = (const float*)d_in[9];
    const float* rel_table = (const float*)d_in[10];
    const float* gsb       = (const float*)d_in[11];
    const float* alpha     = (const float*)d_in[12];
    const float* Wqf       = (const float*)d_in[13];
    const float* bqf       = (const float*)d_in[14];
    const float* Wqp       = (const float*)d_in[15];
    const float* bqp       = (const float*)d_in[16];
    const float* Wo        = (const float*)d_in[17];
    const float* bo        = (const float*)d_in[18];

    float *pWcat, *pConv, *pAttn;
    cudaGetSymbolAddress((void**)&pWcat, g_Wcat);
    cudaGetSymbolAddress((void**)&pConv, g_conv);
    cudaGetSymbolAddress((void**)&pAttn, g_attn);

    // 1. repack conv weights into a single [1536 x 1536] GEMM B matrix
    repack_w<<<(K3 * K3 + 255) / 256, 256>>>(Wq, Wk, Wv);

    // 2. fused QKV conv as one im2col GEMM: [40960 x 1536] @ [1536 x 1536]
    {
        dim3 grid(K3 / BN, Mrows / BM);   // (12, 320)
        sgemm_kernel<1, false><<<grid, 256>>>(x, pWcat, pConv, nullptr,
                                              Mrows, K3, K3);
    }

    // 3. LayerNorm + residual -> q,k,v
    ln_res_kernel<<<3 * Mrows, 256>>>(x, gq_g, gq_b, gk_g, gk_b, gv_g, gv_b);

    // 4. dynamic-bias projection qp
    qp_kernel<<<Mrows / 8, 64>>>(x, Wqf, bqf, Wqp);

    // 5. attention per (b, h)
    attn_kernel<<<Bsz * Hh, 256>>>(rel_table, gsb, alpha, bqp);

    // 6. output projection: [40960 x 512] @ [512 x 512] + bo
    {
        dim3 grid(Dd / BN, Mrows / BM);   // (4, 320)
        sgemm_kernel<0, true><<<grid, 256>>>(pAttn, Wo, (float*)d_out, bo,
                                             Mrows, Dd, Dd);
    }
}

// round 6
// speedup vs baseline: 2.6562x; 2.6562x over previous
#include <cuda_runtime.h>
#include <cuda_bf16.h>
#include <math.h>
#include <stdint.h>
#include <stddef.h>

// ------------ problem constants ------------
#define Bsz   2048
#define Nn    20
#define Dd    512
#define Hh    8
#define Mrows (Bsz*Nn)     // 40960
#define K3    (3*Dd)       // 1536

// ------------ scratch (static __device__) ------------
__device__ __align__(256) float g_conv[(size_t)Mrows * K3];        // conv GEMM out (fp32)
__device__ __align__(256) float g_qkv[(size_t)3 * Mrows * Dd];     // q,k,v after LN+res
__device__ __align__(256) float g_qp[(size_t)Mrows * Hh];
__device__ __align__(256) __nv_bfloat16 g_xh[(size_t)Mrows * Dd];  // x split hi/lo
__device__ __align__(256) __nv_bfloat16 g_xl[(size_t)Mrows * Dd];
__device__ __align__(256) __nv_bfloat16 g_ah[(size_t)Mrows * Dd];  // attn out split
__device__ __align__(256) __nv_bfloat16 g_al[(size_t)Mrows * Dd];
__device__ __align__(256) __nv_bfloat16 g_wth[(size_t)K3 * K3];    // W^T concat [oc][kk]
__device__ __align__(256) __nv_bfloat16 g_wtl[(size_t)K3 * K3];
__device__ __align__(256) __nv_bfloat16 g_woh[(size_t)Dd * Dd];    // Wo^T [n][k]
__device__ __align__(256) __nv_bfloat16 g_wol[(size_t)Dd * Dd];

// ------------ small PTX helpers (all plain-sm_103-safe) ------------
__device__ __forceinline__ uint32_t smem_u32(const void* p) {
    uint32_t a;
    asm("{ .reg .u64 t; cvta.to.shared.u64 t, %1; cvt.u32.u64 %0, t; }" : "=r"(a) : "l"(p));
    return a;
}
__device__ __forceinline__ void cp_async16(uint32_t saddr, const void* gaddr, uint32_t srcsize) {
    asm volatile("cp.async.cg.shared.global [%0], [%1], 16, %2;"
                 :: "r"(saddr), "l"(gaddr), "r"(srcsize) : "memory");
}
__device__ __forceinline__ void cp_commit() { asm volatile("cp.async.commit_group;" ::: "memory"); }
__device__ __forceinline__ void cp_wait0()  { asm volatile("cp.async.wait_group 0;" ::: "memory"); }
__device__ __forceinline__ void cp_wait1()  { asm volatile("cp.async.wait_group 1;" ::: "memory"); }

__device__ __forceinline__ void ldsm4(uint32_t* r, uint32_t addr) {
    asm volatile("ldmatrix.sync.aligned.m8n8.x4.shared.b16 {%0,%1,%2,%3}, [%4];"
                 : "=r"(r[0]), "=r"(r[1]), "=r"(r[2]), "=r"(r[3]) : "r"(addr));
}
__device__ __forceinline__ void mma16816(float* c, const uint32_t* a, const uint32_t* b) {
    asm volatile("mma.sync.aligned.m16n8k16.row.col.f32.bf16.bf16.f32 "
                 "{%0,%1,%2,%3}, {%4,%5,%6,%7}, {%8,%9}, {%0,%1,%2,%3};"
                 : "+f"(c[0]), "+f"(c[1]), "+f"(c[2]), "+f"(c[3])
                 : "r"(a[0]), "r"(a[1]), "r"(a[2]), "r"(a[3]), "r"(b[0]), "r"(b[1]));
}

// ============================================================
// precompute kernels
// ============================================================
__global__ void split_x(const float* __restrict__ x) {
    size_t i = (size_t)blockIdx.x * 256 + threadIdx.x;
    if (i >= (size_t)Mrows * Dd) return;
    float v = x[i];
    __nv_bfloat16 h = __float2bfloat16(v);
    g_xh[i] = h;
    g_xl[i] = __float2bfloat16(v - __bfloat162float(h));
}

// Wt[oc][kk] = W_p[o, i, t], oc = p*512+o, kk = t*512+i  (bf16 hi/lo)
__global__ void repack_w(const float* __restrict__ Wq,
                         const float* __restrict__ Wk,
                         const float* __restrict__ Wv) {
    size_t idx = (size_t)blockIdx.x * 256 + threadIdx.x;
    if (idx >= (size_t)K3 * K3) return;
    int oc = (int)(idx / K3);
    int kk = (int)(idx - (size_t)oc * K3);
    int t = kk >> 9, i = kk & 511;
    int p = oc >> 9, o = oc & 511;
    const float* W = (p == 0) ? Wq : (p == 1) ? Wk : Wv;
    float v = W[(size_t)o * K3 + i * 3 + t];
    __nv_bfloat16 h = __float2bfloat16(v);
    g_wth[idx] = h;
    g_wtl[idx] = __float2bfloat16(v - __bfloat162float(h));
}

// Wot[n][k] = Wo[k][n]
__global__ void repack_wo(const float* __restrict__ Wo) {
    int idx = blockIdx.x * 256 + threadIdx.x;
    if (idx >= Dd * Dd) return;
    int n = idx >> 9, k = idx & 511;
    float v = Wo[(size_t)k * Dd + n];
    __nv_bfloat16 h = __float2bfloat16(v);
    g_woh[idx] = h;
    g_wol[idx] = __float2bfloat16(v - __bfloat162float(h));
}

// ============================================================
// warp-mma bf16 GEMM: C[M x N] = A[M x K] * B^T   (B stored [N x K])
// bf16x3 split: Ah*Bh + Ah*Bl + Al*Bh, fp32 accumulators.
// MODE 1: A gathered via im2col of x (hi/lo arrays, [Mrows x 512]).
// CTA tile 128x128, 8 warps (2x4), warp tile 64x32, BK=32, double buffer.
// smem rows padded: 32 bf16 data + 8 pad = 40 elems (80 B) -> ldmatrix
// phases hit 8 distinct 16B banks (80*r mod 128 is a permutation).
// ============================================================
#define BKc   32
#define LDS_E 40                        // elems per smem row (80 B)
#define TILE_E (128 * LDS_E)            // elems per tile buffer
#define TILE_BYTES (TILE_E * 2)         // 10240 B
#define STAGE_E (4 * TILE_E)            // Ah, Al, Bh, Bl
#define GEMM_SMEM (2 * STAGE_E * 2)     // 2 stages, bytes = 81920

template<int MODE, bool BIAS>
__global__ __launch_bounds__(256, 1)
void tc_gemm(const __nv_bfloat16* __restrict__ Ah, const __nv_bfloat16* __restrict__ Al,
             const __nv_bfloat16* __restrict__ Bh, const __nv_bfloat16* __restrict__ Bl,
             float* __restrict__ C, const float* __restrict__ bias, int K, int N)
{
    extern __shared__ __nv_bfloat16 smem[];   // [2 stages][4 tiles][128][40]
    const uint32_t sb = smem_u32(smem);
    const int tid = threadIdx.x;
    const int wid = tid >> 5, lid = tid & 31;
    const int warp_m = wid >> 2;      // 0..1  (64 rows each)
    const int warp_n = wid & 3;       // 0..3  (32 cols each)
    const int m0 = blockIdx.y * 128, n0 = blockIdx.x * 128;
    const int NC = K >> 5;            // K/32 stages

    // ---- stage loader: 4 tiles x 512 16B-chunks, 256 thr -> 8 chunks each ----
    auto load_stage = [&](int c) {
        const int buf = c & 1;
        const int kk0 = c << 5;
        uint32_t sbase = sb + buf * (STAGE_E * 2);
        #pragma unroll
        for (int it = 0; it < 2; it++) {
            int id = tid + it * 256;            // 0..511
            int r = id >> 2, q = id & 3;        // row, 16B quad (8 elems)
            uint32_t soff = (uint32_t)(r * LDS_E + q * 8) * 2;
            // A (hi & lo)
            size_t aoff; uint32_t vsz = 16;
            if (MODE == 1) {
                int gm = m0 + r;
                int bb = gm / Nn, nn = gm - bb * Nn;
                int t = kk0 >> 9;
                int d = (kk0 & 511) + q * 8;
                int jj = nn + t - 1;
                if (jj < 0 || jj >= Nn) { vsz = 0; jj = 0; }
                aoff = ((size_t)(bb * Nn + jj) << 9) + d;
            } else {
                aoff = (size_t)(m0 + r) * K + kk0 + q * 8;
            }
            cp_async16(sbase + 0 * TILE_BYTES + soff, Ah + aoff, vsz);
            cp_async16(sbase + 1 * TILE_BYTES + soff, Al + aoff, vsz);
            // B (hi & lo)
            size_t boff = (size_t)(n0 + r) * K + kk0 + q * 8;
            cp_async16(sbase + 2 * TILE_BYTES + soff, Bh + boff, 16);
            cp_async16(sbase + 3 * TILE_BYTES + soff, Bl + boff, 16);
        }
        cp_commit();
    };

    float acc[4][4][4];
    #pragma unroll
    for (int i = 0; i < 4; i++)
        #pragma unroll
        for (int j = 0; j < 4; j++)
            #pragma unroll
            for (int e = 0; e < 4; e++) acc[i][j][e] = 0.f;

    load_stage(0);

    // ldmatrix lane addressing (within a [128][40] tile, byte units)
    // A: lanes 0-15 -> rows m 0..15 at kbyte 0; 16-31 -> same rows at kbyte 16
    const uint32_t a_row = (uint32_t)(warp_m * 64 + (lid & 15));
    const uint32_t a_koff = (uint32_t)((lid >> 4) * 16);
    // B: lanes 0-7 n0-7 k0 | 8-15 n0-7 k16 | 16-23 n8-15 k0 | 24-31 n8-15 k16
    const uint32_t b_row = (uint32_t)(warp_n * 32 + ((lid >> 4) * 8) + (lid & 7));
    const uint32_t b_koff = (uint32_t)(((lid >> 3) & 1) * 16);

    for (int c = 0; c < NC; c++) {
        if (c + 1 < NC) { load_stage(c + 1); cp_wait1(); }
        else           { cp_wait0(); }
        __syncthreads();

        const int buf = c & 1;
        const uint32_t sbase = sb + buf * (STAGE_E * 2);
        const uint32_t tAh = sbase + 0 * TILE_BYTES;
        const uint32_t tAl = sbase + 1 * TILE_BYTES;
        const uint32_t tBh = sbase + 2 * TILE_BYTES;
        const uint32_t tBl = sbase + 3 * TILE_BYTES;

        #pragma unroll
        for (int ks = 0; ks < 2; ks++) {
            const uint32_t kb = (uint32_t)(ks * 32);
            uint32_t fah[4][4], fal[4][4], fbh[2][4], fbl[2][4];
            #pragma unroll
            for (int ma = 0; ma < 4; ma++) {
                uint32_t ao = ((a_row + ma * 16) * LDS_E) * 2 + a_koff + kb;
                ldsm4(fah[ma], tAh + ao);
                ldsm4(fal[ma], tAl + ao);
            }
            #pragma unroll
            for (int nb = 0; nb < 2; nb++) {
                uint32_t bo = ((b_row + nb * 16) * LDS_E) * 2 + b_koff + kb;
                ldsm4(fbh[nb], tBh + bo);
                ldsm4(fbl[nb], tBl + bo);
            }
            #pragma unroll
            for (int ma = 0; ma < 4; ma++) {
                #pragma unroll
                for (int na = 0; na < 4; na++) {
                    const uint32_t* bh = &fbh[na >> 1][(na & 1) * 2];
                    const uint32_t* bl = &fbl[na >> 1][(na & 1) * 2];
                    mma16816(acc[ma][na], fah[ma], bh);
                    mma16816(acc[ma][na], fah[ma], bl);
                    mma16816(acc[ma][na], fal[ma], bh);
                }
            }
        }
        __syncthreads();
    }

    // ---- epilogue ----
    const int mrow = m0 + warp_m * 64 + (lid >> 2);
    const int ncol = n0 + warp_n * 32 + (lid & 3) * 2;
    #pragma unroll
    for (int ma = 0; ma < 4; ma++) {
        #pragma unroll
        for (int na = 0; na < 4; na++) {
            int cc = ncol + na * 8;
            float b0 = 0.f, b1 = 0.f;
            if (BIAS) { b0 = bias[cc]; b1 = bias[cc + 1]; }
            float2 v0 = make_float2(acc[ma][na][0] + b0, acc[ma][na][1] + b1);
            float2 v1 = make_float2(acc[ma][na][2] + b0, acc[ma][na][3] + b1);
            *(float2*)(C + (size_t)(mrow + ma * 16)     * N + cc) = v0;
            *(float2*)(C + (size_t)(mrow + ma * 16 + 8) * N + cc) = v1;
        }
    }
}

// ============================================================
// LayerNorm + residual
// ============================================================
__global__ __launch_bounds__(256)
void ln_res_kernel(const float* __restrict__ xin,
                   const float* __restrict__ gq_g, const float* __restrict__ gq_b,
                   const float* __restrict__ gk_g, const float* __restrict__ gk_b,
                   const float* __restrict__ gv_g, const float* __restrict__ gv_b)
{
    int bl = blockIdx.x;
    int p  = bl / Mrows;
    int m  = bl - p * Mrows;
    int tid = threadIdx.x;

    const float* y = g_conv + (size_t)m * K3 + p * Dd;
    float v0 = y[tid];
    float v1 = y[tid + 256];

    __shared__ float rs[256], rq[256];
    rs[tid] = v0 + v1;
    rq[tid] = v0 * v0 + v1 * v1;
    __syncthreads();
    for (int s = 128; s > 0; s >>= 1) {
        if (tid < s) { rs[tid] += rs[tid + s]; rq[tid] += rq[tid + s]; }
        __syncthreads();
    }
    float mean = rs[0] * (1.f / 512.f);
    float var  = rq[0] * (1.f / 512.f) - mean * mean;
    float rstd = rsqrtf(var + 1e-5f);

    const float* g  = (p == 0) ? gq_g : (p == 1) ? gk_g : gv_g;
    const float* bb = (p == 0) ? gq_b : (p == 1) ? gk_b : gv_b;
    float* out = g_qkv + (size_t)p * Mrows * Dd + (size_t)m * Dd;
    const float* xr = xin + (size_t)m * Dd;

    out[tid]       = xr[tid]       + (v0 - mean) * rstd * g[tid]       + bb[tid];
    out[tid + 256] = xr[tid + 256] + (v1 - mean) * rstd * g[tid + 256] + bb[tid + 256];
}

// ============================================================
// qp[b,n,h] = tanh(x @ Wqf + bqf) @ Wqp (dyn bias factorization)
// ============================================================
__global__ __launch_bounds__(64)
void qp_kernel(const float* __restrict__ x, const float* __restrict__ Wqf,
               const float* __restrict__ bqf, const float* __restrict__ Wqp)
{
    __shared__ float xs[8][512];
    __shared__ float qf[8][64];
    int m0 = blockIdx.x * 8;
    int tid = threadIdx.x;

    for (int i = tid; i < 8 * 512; i += 64)
        xs[i >> 9][i & 511] = x[(size_t)m0 * 512 + i];
    __syncthreads();

    float acc[8];
    float bq = bqf[tid];
    #pragma unroll
    for (int r = 0; r < 8; r++) acc[r] = bq;
    for (int i = 0; i < 512; i++) {
        float w = Wqf[i * 64 + tid];
        #pragma unroll
        for (int r = 0; r < 8; r++) acc[r] += xs[r][i] * w;
    }
    #pragma unroll
    for (int r = 0; r < 8; r++) qf[r][tid] = tanhf(acc[r]);
    __syncthreads();

    int r = tid >> 3, h = tid & 7;
    float a = 0.f;
    #pragma unroll
    for (int t = 0; t < 64; t++) a += qf[r][t] * Wqp[t * 8 + h];
    g_qp[(size_t)(m0 + r) * 8 + h] = a;
}

// ============================================================
// Attention per (b, h); writes bf16 hi/lo for the output GEMM.
// ============================================================
__global__ __launch_bounds__(256)
void attn_kernel(const float* __restrict__ rel_table,
                 const float* __restrict__ gsb,
                 const float* __restrict__ alpha_p,
                 const float* __restrict__ bqp)
{
    int b = blockIdx.x >> 3;
    int h = blockIdx.x & 7;
    int tid = threadIdx.x;

    __shared__ float qs[Nn * 64], ks[Nn * 64], vs[Nn * 64];
    __shared__ float sc[Nn][Nn];
    __shared__ float relh[2 * Nn - 1];
    __shared__ float qph[Nn];

    const size_t KOFF = (size_t)Mrows * Dd;
    const size_t VOFF = (size_t)2 * Mrows * Dd;

    for (int i = tid; i < Nn * 64; i += 256) {
        int n = i >> 6, d = i & 63;
        size_t src = (size_t)(b * Nn + n) * Dd + h * 64 + d;
        qs[i] = g_qkv[src];
        ks[i] = g_qkv[KOFF + src];
        vs[i] = g_qkv[VOFF + src];
    }
    if (tid < 2 * Nn - 1) relh[tid] = rel_table[tid * Hh + h];
    if (tid < Nn)         qph[tid]  = g_qp[(size_t)(b * Nn + tid) * Hh + h];
    __syncthreads();

    float alpha = *alpha_p;
    float bq = bqp[h];

    for (int i = tid; i < Nn * Nn; i += 256) {
        int n = i / Nn, m = i - n * Nn;
        float a = 0.f;
        #pragma unroll
        for (int d = 0; d < 64; d++) a += qs[n * 64 + d] * ks[m * 64 + d];
        a = a * 0.125f
          + relh[n - m + Nn - 1]
          + alpha * gsb[(size_t)(h * Nn + n) * Nn + m]
          + (qph[n] - qph[m]) + bq;
        sc[n][m] = a;
    }
    __syncthreads();

    if (tid < Nn) {
        float mx = -1e30f;
        #pragma unroll
        for (int m = 0; m < Nn; m++) mx = fmaxf(mx, sc[tid][m]);
        float s = 0.f;
        #pragma unroll
        for (int m = 0; m < Nn; m++) { float e = expf(sc[tid][m] - mx); sc[tid][m] = e; s += e; }
        float inv = 1.f / s;
        #pragma unroll
        for (int m = 0; m < Nn; m++) sc[tid][m] *= inv;
    }
    __syncthreads();

    for (int i = tid; i < Nn * 64; i += 256) {
        int n = i >> 6, d = i & 63;
        float a = 0.f;
        #pragma unroll
        for (int m = 0; m < Nn; m++) a += sc[n][m] * vs[m * 64 + d];
        size_t dst = (size_t)(b * Nn + n) * Dd + h * 64 + d;
        __nv_bfloat16 hi = __float2bfloat16(a);
        g_ah[dst] = hi;
        g_al[dst] = __float2bfloat16(a - __bfloat162float(hi));
    }
}

// ============================================================
// launch
// ============================================================
extern "C" void kernel_launch(void* const* d_in, const int* in_sizes, int n_in,
                              void* d_out, int out_size)
{
    const float* x         = (const float*)d_in[0];
    const float* Wq        = (const float*)d_in[1];
    const float* Wk        = (const float*)d_in[2];
    const float* Wv        = (const float*)d_in[3];
    const float* gq_g      = (const float*)d_in[4];
    const float* gq_b      = (const float*)d_in[5];
    const float* gk_g      = (const float*)d_in[6];
    const float* gk_b      = (const float*)d_in[7];
    const float* gv_g      = (const float*)d_in[8];
    const float* gv_b      = (const float*)d_in[9];
    const float* rel_table = (const float*)d_in[10];
    const float* gsb       = (const float*)d_in[11];
    const float* alpha     = (const float*)d_in[12];
    const float* Wqf       = (const float*)d_in[13];
    const float* bqf       = (const float*)d_in[14];
    const float* Wqp       = (const float*)d_in[15];
    const float* bqp       = (const float*)d_in[16];
    const float* Wo        = (const float*)d_in[17];
    const float* bo        = (const float*)d_in[18];

    cudaFuncSetAttribute(tc_gemm<1, false>, cudaFuncAttributeMaxDynamicSharedMemorySize, GEMM_SMEM);
    cudaFuncSetAttribute(tc_gemm<0, true>,  cudaFuncAttributeMaxDynamicSharedMemorySize, GEMM_SMEM);

    __nv_bfloat16 *pxh, *pxl, *pwth, *pwtl, *pah, *pal, *pwoh, *pwol;
    float *pConv;
    cudaGetSymbolAddress((void**)&pxh, g_xh);
    cudaGetSymbolAddress((void**)&pxl, g_xl);
    cudaGetSymbolAddress((void**)&pwth, g_wth);
    cudaGetSymbolAddress((void**)&pwtl, g_wtl);
    cudaGetSymbolAddress((void**)&pah, g_ah);
    cudaGetSymbolAddress((void**)&pal, g_al);
    cudaGetSymbolAddress((void**)&pwoh, g_woh);
    cudaGetSymbolAddress((void**)&pwol, g_wol);
    cudaGetSymbolAddress((void**)&pConv, g_conv);

    // 1. precompute bf16 hi/lo splits
    split_x<<<(Mrows * Dd + 255) / 256, 256>>>(x);
    repack_w<<<(K3 * K3 + 255) / 256, 256>>>(Wq, Wk, Wv);
    repack_wo<<<(Dd * Dd + 255) / 256, 256>>>(Wo);

    // 2. fused QKV conv as im2col GEMM: [40960 x 1536] = im2col(x) @ Wcat
    {
        dim3 grid(K3 / 128, Mrows / 128);   // (12, 320)
        tc_gemm<1, false><<<grid, 256, GEMM_SMEM>>>(pxh, pxl, pwth, pwtl,
                                                    pConv, nullptr, K3, K3);
    }

    // 3. LayerNorm + residual -> q,k,v
    ln_res_kernel<<<3 * Mrows, 256>>>(x, gq_g, gq_b, gk_g, gk_b, gv_g, gv_b);

    // 4. dynamic-bias projection qp
    qp_kernel<<<Mrows / 8, 64>>>(x, Wqf, bqf, Wqp);

    // 5. attention per (b, h), emits bf16 hi/lo
    attn_kernel<<<Bsz * Hh, 256>>>(rel_table, gsb, alpha, bqp);

    // 6. output projection: [40960 x 512] @ Wo + bo
    {
        dim3 grid(Dd / 128, Mrows / 128);   // (4, 320)
        tc_gemm<0, true><<<grid, 256, GEMM_SMEM>>>(pah, pal, pwoh, pwol,
                                                   (float*)d_out, bo, Dd, Dd);
    }
}